// round 6
// baseline (speedup 1.0000x reference)
#include <cuda_runtime.h>
#include <cstdint>

// out = y * (mean(x,-1) + mean(y,-1)),  [64, 36, 4096] fp32, rows = 2304.
//
// Round-6 structure: split input streams across the SM's two memory paths.
//   x : LDG.128 (L1tex path), reduced straight from registers, never in smem.
//   y : 1D bulk TMA (async path) -> smem, double-buffered, kept in regs for
//       the scaled store.
// 4 persistent CTAs/SM x 2 stages = 8 rows in flight per SM.
// Everything (x, y loads AND out stores) carries L2::evict_last: the full
// 113 MB working set fits the 126 MB L2, so steady-state graph replays
// rewrite out-lines in place in L2 instead of streaming them to DRAM.

constexpr int L_LEN     = 4096;
constexpr int NTHREADS  = 256;
constexpr int ITERS     = L_LEN / (NTHREADS * 4);   // 4 float4 per thread
constexpr int ROW_BYTES = L_LEN * 4;                // 16 KB
constexpr int DYN_SMEM  = 2 * ROW_BYTES;            // two y stages, 32 KB

__device__ __forceinline__ uint32_t smem_u32(const void* p) {
    return (uint32_t)__cvta_generic_to_shared(p);
}

__device__ __forceinline__ void mbar_init(uint32_t mbar, uint32_t count) {
    asm volatile("mbarrier.init.shared.b64 [%0], %1;" :: "r"(mbar), "r"(count) : "memory");
}

__device__ __forceinline__ void mbar_expect_tx(uint32_t mbar, uint32_t bytes) {
    asm volatile("mbarrier.arrive.expect_tx.shared.b64 _, [%0], %1;"
                 :: "r"(mbar), "r"(bytes) : "memory");
}

__device__ __forceinline__ uint64_t l2_evict_last_policy() {
    uint64_t pol;
    asm volatile("createpolicy.fractional.L2::evict_last.b64 %0, 1.0;" : "=l"(pol));
    return pol;
}

__device__ __forceinline__ void bulk_ld_pin(uint32_t dst_smem, const void* src,
                                            uint32_t bytes, uint32_t mbar, uint64_t pol) {
    asm volatile(
        "cp.async.bulk.shared::cluster.global.mbarrier::complete_tx::bytes.L2::cache_hint "
        "[%0], [%1], %2, [%3], %4;"
        :: "r"(dst_smem), "l"(src), "r"(bytes), "r"(mbar), "l"(pol) : "memory");
}

__device__ __forceinline__ void mbar_wait(uint32_t mbar, uint32_t parity) {
    uint32_t done;
    asm volatile(
        "{\n\t"
        ".reg .pred p;\n\t"
        "mbarrier.try_wait.parity.acquire.cta.shared::cta.b64 p, [%1], %2;\n\t"
        "selp.b32 %0, 1, 0, p;\n\t"
        "}"
        : "=r"(done) : "r"(mbar), "r"(parity) : "memory");
    if (!done) {
        asm volatile(
            "{\n\t"
            ".reg .pred P1;\n\t"
            "WAIT_LOOP_%=:\n\t"
            "mbarrier.try_wait.parity.acquire.cta.shared::cta.b64 P1, [%0], %1, 0x989680;\n\t"
            "@P1 bra.uni WAIT_DONE_%=;\n\t"
            "bra.uni WAIT_LOOP_%=;\n\t"
            "WAIT_DONE_%=:\n\t"
            "}"
            :: "r"(mbar), "r"(parity) : "memory");
    }
}

__device__ __forceinline__ float4 ldg_pin_f4(const float4* p, uint64_t pol) {
    float4 v;
    asm volatile("ld.global.nc.L2::cache_hint.v4.f32 {%0,%1,%2,%3}, [%4], %5;"
                 : "=f"(v.x), "=f"(v.y), "=f"(v.z), "=f"(v.w)
                 : "l"(p), "l"(pol));
    return v;
}

__device__ __forceinline__ void stg_pin_f4(float4* p, float4 v, uint64_t pol) {
    asm volatile("st.global.L2::cache_hint.v4.f32 [%0], {%1,%2,%3,%4}, %5;"
                 :: "l"(p), "f"(v.x), "f"(v.y), "f"(v.z), "f"(v.w), "l"(pol)
                 : "memory");
}

__global__ __launch_bounds__(NTHREADS, 4)
void spo2_split_kernel(const float* __restrict__ x,
                       const float* __restrict__ y,
                       float* __restrict__ out,
                       int nrows)
{
    extern __shared__ float sy_stages[];   // [2][4096] floats
    __shared__ alignas(8) unsigned long long mbar_storage[2];
    __shared__ float warpsum[NTHREADS / 32];

    const int tid = threadIdx.x;
    const uint32_t mb[2] = { smem_u32(&mbar_storage[0]), smem_u32(&mbar_storage[1]) };
    const uint64_t pol = l2_evict_last_policy();

    if (tid == 0) {
        mbar_init(mb[0], 1);
        mbar_init(mb[1], 1);
    }
    __syncthreads();

    const int stride = gridDim.x;
    const int row0 = blockIdx.x;

    // Prologue: y of row0 into stage 0.
    if (tid == 0 && row0 < nrows) {
        const size_t base = (size_t)row0 * L_LEN;
        mbar_expect_tx(mb[0], ROW_BYTES);
        bulk_ld_pin(smem_u32(sy_stages), y + base, ROW_BYTES, mb[0], pol);
    }

    int phase0 = 0, phase1 = 0;
    int k = 0;
    for (int row = row0; row < nrows; row += stride, k++) {
        const int s = k & 1;
        const size_t base = (size_t)row * L_LEN;

        // Prefetch next row's y into the other stage before waiting.
        const int nrow = row + stride;
        if (tid == 0 && nrow < nrows) {
            const int ns = 1 - s;
            mbar_expect_tx(mb[ns], ROW_BYTES);
            bulk_ld_pin(smem_u32(sy_stages + ns * L_LEN),
                        y + (size_t)nrow * L_LEN, ROW_BYTES, mb[ns], pol);
        }

        // x on the LDG/L1tex path, reduced from registers (overlaps with
        // the in-flight y TMA).
        const float4* xr = reinterpret_cast<const float4*>(x + base);
        float t = 0.0f;
        {
            float4 xv[ITERS];
#pragma unroll
            for (int i = 0; i < ITERS; i++)
                xv[i] = ldg_pin_f4(&xr[i * NTHREADS + tid], pol);
#pragma unroll
            for (int i = 0; i < ITERS; i++)
                t += (xv[i].x + xv[i].y) + (xv[i].z + xv[i].w);
        }

        // Wait for this row's y, reduce it from smem, keep it in regs.
        if (s == 0) { mbar_wait(mb[0], phase0); phase0 ^= 1; }
        else        { mbar_wait(mb[1], phase1); phase1 ^= 1; }

        const float4* sy4 = reinterpret_cast<const float4*>(sy_stages + s * L_LEN);
        float4 yv[ITERS];
#pragma unroll
        for (int i = 0; i < ITERS; i++) {
            yv[i] = sy4[i * NTHREADS + tid];
            t += (yv[i].x + yv[i].y) + (yv[i].z + yv[i].w);
        }

        // Block reduction -> sc = (sum_x + sum_y)/L
#pragma unroll
        for (int o = 16; o > 0; o >>= 1)
            t += __shfl_xor_sync(0xffffffffu, t, o);
        if ((tid & 31) == 0)
            warpsum[tid >> 5] = t;
        __syncthreads();
        if (tid < 32) {
            float v = (tid < NTHREADS / 32) ? warpsum[tid] : 0.0f;
#pragma unroll
            for (int o = 4; o > 0; o >>= 1)
                v += __shfl_xor_sync(0xffffffffu, v, o);
            if (tid == 0)
                warpsum[0] = v;
        }
        __syncthreads();
        // All smem reads of stage s done past this barrier -> safe to
        // re-issue TMA into stage s next iteration.

        const float sc = warpsum[0] * (1.0f / (float)L_LEN);

        // Scaled store; evict_last so out-lines are rewritten in place in L2
        // across graph replays instead of streaming to DRAM.
        float4* orow = reinterpret_cast<float4*>(out + base);
#pragma unroll
        for (int i = 0; i < ITERS; i++) {
            float4 v = yv[i];
            v.x *= sc; v.y *= sc; v.z *= sc; v.w *= sc;
            stg_pin_f4(&orow[i * NTHREADS + tid], v, pol);
        }
    }
}

extern "C" void kernel_launch(void* const* d_in, const int* in_sizes, int n_in,
                              void* d_out, int out_size)
{
    const float* x = (const float*)d_in[0];
    const float* y = (const float*)d_in[1];
    float* out = (float*)d_out;

    const int nrows = in_sizes[0] / L_LEN;   // 2304

    cudaFuncSetAttribute(spo2_split_kernel,
                         cudaFuncAttributeMaxDynamicSharedMemorySize, DYN_SMEM);

    int grid = 4 * 148;                      // 4 persistent CTAs per SM
    if (grid > nrows) grid = nrows;
    spo2_split_kernel<<<grid, NTHREADS, DYN_SMEM>>>(x, y, out, nrows);
}

// round 7
// speedup vs baseline: 1.0927x; 1.0927x over previous
#include <cuda_runtime.h>
#include <cstdint>

// out = y * (mean(x,-1) + mean(y,-1)),  [64, 36, 4096] fp32, rows = 2304.
//
// R7 = R5's best-known load pipeline (persistent 3 CTAs/SM, double-buffered
// 1D bulk-TMA loads of x,y into SMEM, no cache hints) with ONE change:
// the output goes out via bulk TMA STORE. Threads scale y in place in SMEM,
// then thread 0 issues a single 16 KB cp.async.bulk store per row. The
// register->STG.128 path (the only component common to every previous
// kernel) is eliminated; stage reuse is guarded by bulk wait_group.

constexpr int L_LEN     = 4096;
constexpr int NTHREADS  = 256;
constexpr int ITERS     = L_LEN / (NTHREADS * 4);   // 4 float4 per thread
constexpr int ROW_BYTES = L_LEN * 4;                // 16 KB
constexpr int STAGE_FLOATS = 2 * L_LEN;             // [x 4096][y 4096], 32 KB
constexpr int DYN_SMEM  = 2 * STAGE_FLOATS * 4;     // two stages, 64 KB

__device__ __forceinline__ uint32_t smem_u32(const void* p) {
    return (uint32_t)__cvta_generic_to_shared(p);
}

__device__ __forceinline__ void mbar_init(uint32_t mbar, uint32_t count) {
    asm volatile("mbarrier.init.shared.b64 [%0], %1;" :: "r"(mbar), "r"(count) : "memory");
}

__device__ __forceinline__ void mbar_expect_tx(uint32_t mbar, uint32_t bytes) {
    asm volatile("mbarrier.arrive.expect_tx.shared.b64 _, [%0], %1;"
                 :: "r"(mbar), "r"(bytes) : "memory");
}

__device__ __forceinline__ void bulk_ld(uint32_t dst_smem, const void* src, uint32_t bytes,
                                        uint32_t mbar) {
    asm volatile(
        "cp.async.bulk.shared::cluster.global.mbarrier::complete_tx::bytes "
        "[%0], [%1], %2, [%3];"
        :: "r"(dst_smem), "l"(src), "r"(bytes), "r"(mbar) : "memory");
}

__device__ __forceinline__ void bulk_st(void* dst, uint32_t src_smem, uint32_t bytes) {
    asm volatile(
        "cp.async.bulk.global.shared::cta.bulk_group [%0], [%1], %2;"
        :: "l"(dst), "r"(src_smem), "r"(bytes) : "memory");
}

__device__ __forceinline__ void bulk_st_commit() {
    asm volatile("cp.async.bulk.commit_group;" ::: "memory");
}

template <int N>
__device__ __forceinline__ void bulk_st_wait() {
    asm volatile("cp.async.bulk.wait_group %0;" :: "n"(N) : "memory");
}

__device__ __forceinline__ void mbar_wait(uint32_t mbar, uint32_t parity) {
    uint32_t done;
    asm volatile(
        "{\n\t"
        ".reg .pred p;\n\t"
        "mbarrier.try_wait.parity.acquire.cta.shared::cta.b64 p, [%1], %2;\n\t"
        "selp.b32 %0, 1, 0, p;\n\t"
        "}"
        : "=r"(done) : "r"(mbar), "r"(parity) : "memory");
    if (!done) {
        asm volatile(
            "{\n\t"
            ".reg .pred P1;\n\t"
            "WAIT_LOOP_%=:\n\t"
            "mbarrier.try_wait.parity.acquire.cta.shared::cta.b64 P1, [%0], %1, 0x989680;\n\t"
            "@P1 bra.uni WAIT_DONE_%=;\n\t"
            "bra.uni WAIT_LOOP_%=;\n\t"
            "WAIT_DONE_%=:\n\t"
            "}"
            :: "r"(mbar), "r"(parity) : "memory");
    }
}

__global__ __launch_bounds__(NTHREADS)
void spo2_tmastore_kernel(const float* __restrict__ x,
                          const float* __restrict__ y,
                          float* __restrict__ out,
                          int nrows)
{
    extern __shared__ float sbuf[];   // stage s at sbuf + s*STAGE_FLOATS
    __shared__ alignas(8) unsigned long long mbar_storage[2];
    __shared__ float warpsum[NTHREADS / 32];

    const int tid = threadIdx.x;
    const uint32_t mb[2] = { smem_u32(&mbar_storage[0]), smem_u32(&mbar_storage[1]) };

    if (tid == 0) {
        mbar_init(mb[0], 1);
        mbar_init(mb[1], 1);
    }
    __syncthreads();

    const int stride = gridDim.x;
    const int row0 = blockIdx.x;

    // Prologue: row0 into stage 0.
    if (tid == 0 && row0 < nrows) {
        const size_t base = (size_t)row0 * L_LEN;
        mbar_expect_tx(mb[0], 2 * ROW_BYTES);
        bulk_ld(smem_u32(sbuf),         x + base, ROW_BYTES, mb[0]);
        bulk_ld(smem_u32(sbuf + L_LEN), y + base, ROW_BYTES, mb[0]);
    }

    int phase0 = 0, phase1 = 0;
    int k = 0;
    for (int row = row0; row < nrows; row += stride, k++) {
        const int s = k & 1;

        // Prefetch the NEXT row into the other stage. Before overwriting it,
        // drain any pending bulk store that still reads from that stage
        // (issued two iterations ago; should be long complete).
        const int nrow = row + stride;
        if (tid == 0 && nrow < nrows) {
            const int ns = 1 - s;
            bulk_st_wait<0>();
            const size_t nbase = (size_t)nrow * L_LEN;
            float* nstage = sbuf + ns * STAGE_FLOATS;
            mbar_expect_tx(mb[ns], 2 * ROW_BYTES);
            bulk_ld(smem_u32(nstage),         x + nbase, ROW_BYTES, mb[ns]);
            bulk_ld(smem_u32(nstage + L_LEN), y + nbase, ROW_BYTES, mb[ns]);
        }

        if (s == 0) { mbar_wait(mb[0], phase0); phase0 ^= 1; }
        else        { mbar_wait(mb[1], phase1); phase1 ^= 1; }

        float* ystage = sbuf + s * STAGE_FLOATS + L_LEN;
        const float4* sx4 = reinterpret_cast<const float4*>(sbuf + s * STAGE_FLOATS);
        const float4* sy4 = reinterpret_cast<const float4*>(ystage);

        float4 yv[ITERS];
        float t = 0.0f;
#pragma unroll
        for (int i = 0; i < ITERS; i++) {
            const int idx = i * NTHREADS + tid;
            float4 a = sx4[idx];
            yv[i] = sy4[idx];
            t += (a.x + a.y) + (a.z + a.w);
            t += (yv[i].x + yv[i].y) + (yv[i].z + yv[i].w);
        }

        // Block reduction -> sc = (sum_x + sum_y)/L
#pragma unroll
        for (int o = 16; o > 0; o >>= 1)
            t += __shfl_xor_sync(0xffffffffu, t, o);
        if ((tid & 31) == 0)
            warpsum[tid >> 5] = t;
        __syncthreads();
        if (tid < 32) {
            float v = (tid < NTHREADS / 32) ? warpsum[tid] : 0.0f;
#pragma unroll
            for (int o = 4; o > 0; o >>= 1)
                v += __shfl_xor_sync(0xffffffffu, v, o);
            if (tid == 0)
                warpsum[0] = v;
        }
        __syncthreads();

        const float sc = warpsum[0] * (1.0f / (float)L_LEN);

        // Scale y in place in SMEM, then TMA-store the row.
        float4* syw = reinterpret_cast<float4*>(ystage);
#pragma unroll
        for (int i = 0; i < ITERS; i++) {
            const int idx = i * NTHREADS + tid;
            float4 v = yv[i];
            v.x *= sc; v.y *= sc; v.z *= sc; v.w *= sc;
            syw[idx] = v;
        }
        __syncthreads();   // all STS visible before the async-proxy read

        if (tid == 0) {
            asm volatile("fence.proxy.async.shared::cta;" ::: "memory");
            bulk_st(out + (size_t)row * L_LEN, smem_u32(ystage), ROW_BYTES);
            bulk_st_commit();
        }
    }

    // Epilogue: make sure the final store lands before the CTA exits.
    if (tid == 0)
        bulk_st_wait<0>();
}

extern "C" void kernel_launch(void* const* d_in, const int* in_sizes, int n_in,
                              void* d_out, int out_size)
{
    const float* x = (const float*)d_in[0];
    const float* y = (const float*)d_in[1];
    float* out = (float*)d_out;

    const int nrows = in_sizes[0] / L_LEN;   // 2304

    cudaFuncSetAttribute(spo2_tmastore_kernel,
                         cudaFuncAttributeMaxDynamicSharedMemorySize, DYN_SMEM);

    int grid = 3 * 148;                      // 3 persistent CTAs per SM
    if (grid > nrows) grid = nrows;
    spo2_tmastore_kernel<<<grid, NTHREADS, DYN_SMEM>>>(x, y, out, nrows);
}